// round 5
// baseline (speedup 1.0000x reference)
#include <cuda_runtime.h>
#include <math.h>
#include <stdint.h>

#define EMB   768
#define MROWS 1024
#define NN    128      // n (softmax) dim
#define KK    128      // attention hidden dim (rows of Wa)
#define XROWS (3*EMB+2) // 2306 rows per m in X
#define TE    32       // e-tile for the attend GEMM

// ---------------- device scratch (no cudaMalloc allowed) ----------------
__device__ float g_WaT[2 * EMB * KK];     // WaT[e][k] = Wa[k][e]   (786 KB)
__device__ float g_Wc [EMB * EMB];        // Wc = W2 @ W1           (2.25 MB)
__device__ float g_bc [EMB];              // bc = W2 @ b1 + b2
__device__ float g_P  [(size_t)MROWS * 3 * EMB]; // [m][{p1,p2,qv}][e]
__device__ float g_Z  [(size_t)MROWS * 3 * EMB]; // mlp outputs

// ---------------- 0) transpose Wa (128 x 1536) -> WaT (1536 x 128) ------
__global__ void k_transpose(const float* __restrict__ Wa) {
    __shared__ float tile[32][33];
    int e = blockIdx.x * 32 + threadIdx.x;   // 0..1535
    int k = blockIdx.y * 32 + threadIdx.y;   // 0..127
#pragma unroll
    for (int j = 0; j < 32; j += 8)
        tile[threadIdx.y + j][threadIdx.x] = Wa[(size_t)(k + j) * (2 * EMB) + e];
    __syncthreads();
    int k2 = blockIdx.y * 32 + threadIdx.x;
    int e2 = blockIdx.x * 32 + threadIdx.y;
#pragma unroll
    for (int j = 0; j < 32; j += 8)
        g_WaT[(size_t)(e2 + j) * KK + k2] = tile[threadIdx.x][threadIdx.y + j];
}

// ---------------- 1) Wc = W2 @ W1 (768x768x768) --------------------------
__global__ void k_wc(const float* __restrict__ W1, const float* __restrict__ W2) {
    __shared__ float As[64][17];   // W2 [i][t]
    __shared__ float Bs[16][65];   // W1 [t][e]
    int i0 = blockIdx.y * 64, e0 = blockIdx.x * 64;
    int tx = threadIdx.x & 15, ty = threadIdx.x >> 4;
    float acc[4][4];
#pragma unroll
    for (int i = 0; i < 4; i++)
#pragma unroll
        for (int j = 0; j < 4; j++) acc[i][j] = 0.f;

    for (int t0 = 0; t0 < EMB; t0 += 16) {
        __syncthreads();
        int idx = threadIdx.x;
#pragma unroll
        for (int rep = 0; rep < 4; rep++, idx += 256) {
            int r = idx >> 4, c = idx & 15;
            As[r][c] = W2[(size_t)(i0 + r) * EMB + t0 + c];
        }
        idx = threadIdx.x;
#pragma unroll
        for (int rep = 0; rep < 4; rep++, idx += 256) {
            int r = idx >> 6, c = idx & 63;
            Bs[r][c] = W1[(size_t)(t0 + r) * EMB + e0 + c];
        }
        __syncthreads();
#pragma unroll
        for (int t = 0; t < 16; t++) {
            float a[4], b[4];
#pragma unroll
            for (int u = 0; u < 4; u++) { a[u] = As[ty * 4 + u][t]; b[u] = Bs[t][tx * 4 + u]; }
#pragma unroll
            for (int i = 0; i < 4; i++)
#pragma unroll
                for (int j = 0; j < 4; j++) acc[i][j] += a[i] * b[j];
        }
    }
#pragma unroll
    for (int i = 0; i < 4; i++)
#pragma unroll
        for (int j = 0; j < 4; j++)
            g_Wc[(size_t)(i0 + ty * 4 + i) * EMB + e0 + tx * 4 + j] = acc[i][j];
}

// ---------------- 1b) bc = W2 @ b1 + b2 ----------------------------------
__global__ void k_bc(const float* __restrict__ W2, const float* __restrict__ b1,
                     const float* __restrict__ b2) {
    int i = blockIdx.x * blockDim.x + threadIdx.x;
    if (i < EMB) {
        float s = 0.f;
        for (int j = 0; j < EMB; j++) s += W2[(size_t)i * EMB + j] * b1[j];
        g_bc[i] = s + b2[i];
    }
}

// ---------------- 2) attend + softmax + pooling (one block per m) --------
// smem float layout
#define SH_H    0        // 128*128
#define SH_X    16384    // 32*128
#define SH_W    20480    // 32*128
#define SH_SC   24576    // 128
#define SH_BETA 24704    // 128
#define SH_RED  24832    // 32
#define SH_VA   24864    // 128
#define SH_TOT  24992    // floats -> 99968 bytes

__device__ __forceinline__ void gemm_tile(float (&acc)[8][8],
                                          const float* __restrict__ Xbase,
                                          const float* __restrict__ Wbase,
                                          float* sm, int tid, int tx, int ty) {
    float4* xs = (float4*)(sm + SH_X);
    float4* ws = (float4*)(sm + SH_W);
#pragma unroll 1
    for (int t = 0; t < EMB; t += TE) {
        __syncthreads();
        const float4* xg = (const float4*)(Xbase + (size_t)t * NN);
        const float4* wg = (const float4*)(Wbase + (size_t)t * KK);
#pragma unroll
        for (int r = 0; r < 4; r++) {
            int idx = tid + r * 256;          // covers 32 rows * 32 float4
            xs[idx] = xg[idx];
            ws[idx] = wg[idx];
        }
        __syncthreads();
#pragma unroll 8
        for (int e = 0; e < TE; e++) {
            float4 b0 = xs[e * 32 + tx * 2];
            float4 b1 = xs[e * 32 + tx * 2 + 1];
            float4 a0 = ws[e * 32 + ty * 2];
            float4 a1 = ws[e * 32 + ty * 2 + 1];
            float a[8] = {a0.x, a0.y, a0.z, a0.w, a1.x, a1.y, a1.z, a1.w};
            float b[8] = {b0.x, b0.y, b0.z, b0.w, b1.x, b1.y, b1.z, b1.w};
#pragma unroll
            for (int i = 0; i < 8; i++)
#pragma unroll
                for (int j = 0; j < 8; j++) acc[i][j] += a[i] * b[j];
        }
    }
}

__global__ __launch_bounds__(256, 2)
void k_attend(const float* __restrict__ X, const float* __restrict__ va) {
    extern __shared__ float sm[];
    int m   = blockIdx.x;
    int tid = threadIdx.x;
    int tx  = tid & 15, ty = tid >> 4;
    const float* Xm = X + (size_t)m * XROWS * NN;

    if (tid < 128) sm[SH_VA + tid] = va[tid];

    float acc[8][8];

    // ---- Phase A: hq = Wa_q @ Xq -> sh_h ----
#pragma unroll
    for (int i = 0; i < 8; i++)
#pragma unroll
        for (int j = 0; j < 8; j++) acc[i][j] = 0.f;
    gemm_tile(acc, Xm, g_WaT, sm, tid, tx, ty);
#pragma unroll
    for (int i = 0; i < 8; i++) {
        float4 v0 = make_float4(acc[i][0], acc[i][1], acc[i][2], acc[i][3]);
        float4 v1 = make_float4(acc[i][4], acc[i][5], acc[i][6], acc[i][7]);
        ((float4*)(sm + SH_H))[(ty * 8 + i) * 32 + tx * 2]     = v0;
        ((float4*)(sm + SH_H))[(ty * 8 + i) * 32 + tx * 2 + 1] = v1;
    }
    __syncthreads();

    // ---- two pools ----
#pragma unroll 1
    for (int pool = 0; pool < 2; pool++) {
        const int exp0 = (pool == 0) ? EMB : (2 * EMB + 1);       // Xp offset
        const int ev   = (pool == 0) ? (2 * EMB) : (3 * EMB + 1); // valid row

        // hp GEMM
#pragma unroll
        for (int i = 0; i < 8; i++)
#pragma unroll
            for (int j = 0; j < 8; j++) acc[i][j] = 0.f;
        gemm_tile(acc, Xm + (size_t)exp0 * NN, g_WaT + (size_t)EMB * KK,
                  sm, tid, tx, ty);

        // score[n] = sum_k va[k] * tanh(hq + hp)
        if (tid < 128) sm[SH_SC + tid] = 0.f;
        __syncthreads();
        float sj[8];
#pragma unroll
        for (int j = 0; j < 8; j++) sj[j] = 0.f;
#pragma unroll
        for (int i = 0; i < 8; i++) {
            int k = ty * 8 + i;
            float vk = sm[SH_VA + k];
#pragma unroll
            for (int j = 0; j < 8; j++) {
                float h = tanhf(acc[i][j] + sm[SH_H + k * 128 + tx * 8 + j]);
                sj[j] += vk * h;
            }
        }
#pragma unroll
        for (int j = 0; j < 8; j++) atomicAdd(&sm[SH_SC + tx * 8 + j], sj[j]);
        __syncthreads();

        // apply valid mask, softmax over n (128)
        if (tid < 128)
            sm[SH_SC + tid] *= Xm[(size_t)ev * NN + tid];
        __syncthreads();
        if (tid < 32) {
            float mx = fmaxf(fmaxf(sm[SH_SC + tid],      sm[SH_SC + tid + 32]),
                             fmaxf(sm[SH_SC + tid + 64], sm[SH_SC + tid + 96]));
#pragma unroll
            for (int off = 16; off; off >>= 1)
                mx = fmaxf(mx, __shfl_xor_sync(0xffffffffu, mx, off));
            if (tid == 0) sm[SH_RED] = mx;
        }
        __syncthreads();
        float mx = sm[SH_RED];
        if (tid < 128) sm[SH_BETA + tid] = expf(sm[SH_SC + tid] - mx);
        __syncthreads();
        if (tid < 32) {
            float s = sm[SH_BETA + tid] + sm[SH_BETA + tid + 32] +
                      sm[SH_BETA + tid + 64] + sm[SH_BETA + tid + 96];
#pragma unroll
            for (int off = 16; off; off >>= 1)
                s += __shfl_xor_sync(0xffffffffu, s, off);
            if (tid == 0) sm[SH_RED] = s;
        }
        __syncthreads();
        float inv = 1.f / sm[SH_RED];
        if (tid < 128) sm[SH_BETA + tid] *= inv;
        __syncthreads();

        // pooling: p[e] = sum_n beta[n] * Xp[e][n]
        int w = tid >> 5, l = tid & 31;
        for (int e = w; e < EMB; e += 8) {
            const float* row = Xm + (size_t)(exp0 + e) * NN;
            float s = row[l]      * sm[SH_BETA + l]      +
                      row[l + 32] * sm[SH_BETA + l + 32] +
                      row[l + 64] * sm[SH_BETA + l + 64] +
                      row[l + 96] * sm[SH_BETA + l + 96];
#pragma unroll
            for (int off = 16; off; off >>= 1)
                s += __shfl_xor_sync(0xffffffffu, s, off);
            if (l == 0) g_P[((size_t)m * 3 + pool) * EMB + e] = s;
        }
        __syncthreads();
    }

    // qv[e] = Xq[e][0]
    for (int e = tid; e < EMB; e += 256)
        g_P[((size_t)m * 3 + 2) * EMB + e] = Xm[(size_t)e * NN];
}

// ---------------- 3) MLP: Z = relu(P(3072x768) @ Wc^T + bc) --------------
__global__ __launch_bounds__(256) void k_mlp() {
    __shared__ float As[64][33];
    __shared__ float Bs[64][33];
    int r0 = blockIdx.x * 64, i0 = blockIdx.y * 64;
    int tx = threadIdx.x & 15, ty = threadIdx.x >> 4;
    float acc[4][4];
#pragma unroll
    for (int i = 0; i < 4; i++)
#pragma unroll
        for (int j = 0; j < 4; j++) acc[i][j] = 0.f;

    for (int e0 = 0; e0 < EMB; e0 += 32) {
        __syncthreads();
        for (int idx = threadIdx.x; idx < 64 * 32; idx += 256) {
            int r = idx >> 5, c = idx & 31;
            As[r][c] = g_P[(size_t)(r0 + r) * EMB + e0 + c];
            Bs[r][c] = g_Wc[(size_t)(i0 + r) * EMB + e0 + c];
        }
        __syncthreads();
#pragma unroll 8
        for (int ec = 0; ec < 32; ec++) {
            float a[4], b[4];
#pragma unroll
            for (int u = 0; u < 4; u++) {
                a[u] = As[ty * 4 + u][ec];
                b[u] = Bs[tx * 4 + u][ec];
            }
#pragma unroll
            for (int i = 0; i < 4; i++)
#pragma unroll
                for (int j = 0; j < 4; j++) acc[i][j] += a[i] * b[j];
        }
    }
#pragma unroll
    for (int i = 0; i < 4; i++)
#pragma unroll
        for (int j = 0; j < 4; j++) {
            int r = r0 + ty * 4 + i, ii = i0 + tx * 4 + j;
            g_Z[(size_t)r * EMB + ii] = fmaxf(acc[i][j] + g_bc[ii], 0.f);
        }
}

// ---------------- 4) final head ------------------------------------------
__global__ void k_final(const float* __restrict__ W3, const float* __restrict__ b3,
                        float* __restrict__ out) {
    __shared__ float red[8];
    int m = blockIdx.x;
    const float* z1 = g_Z + (size_t)m * 3 * EMB;
    const float* z2 = z1 + EMB;
    const float* zq = z1 + 2 * EMB;
    float s = 0.f;
    for (int i = threadIdx.x; i < EMB; i += 256) {
        float a = z1[i], b = z2[i], q = zq[i];
        s += W3[i] * a + W3[EMB + i] * b +
             W3[2 * EMB + i] * fabsf(a - b) +
             W3[3 * EMB + i] * fabsf(a - q) +
             W3[4 * EMB + i] * fabsf(b - q);
    }
#pragma unroll
    for (int off = 16; off; off >>= 1)
        s += __shfl_xor_sync(0xffffffffu, s, off);
    if ((threadIdx.x & 31) == 0) red[threadIdx.x >> 5] = s;
    __syncthreads();
    if (threadIdx.x == 0) {
        float t = 0.f;
#pragma unroll
        for (int w = 0; w < 8; w++) t += red[w];
        out[m] = fmaxf(t + b3[0], 0.f);
    }
}

// ---------------- launch --------------------------------------------------
extern "C" void kernel_launch(void* const* d_in, const int* in_sizes, int n_in,
                              void* d_out, int out_size) {
    (void)in_sizes; (void)n_in; (void)out_size;
    const float* X  = (const float*)d_in[0];
    const float* Wa = (const float*)d_in[1];
    const float* va = (const float*)d_in[2];
    const float* W1 = (const float*)d_in[3];
    const float* b1 = (const float*)d_in[4];
    const float* W2 = (const float*)d_in[5];
    const float* b2 = (const float*)d_in[6];
    const float* W3 = (const float*)d_in[7];
    const float* b3 = (const float*)d_in[8];
    float* out = (float*)d_out;

    static int smem_set = 0;
    if (!smem_set) {
        cudaFuncSetAttribute(k_attend, cudaFuncAttributeMaxDynamicSharedMemorySize,
                             SH_TOT * (int)sizeof(float));
        smem_set = 1;
    }

    k_transpose<<<dim3(48, 4), dim3(32, 8)>>>(Wa);
    k_wc<<<dim3(12, 12), 256>>>(W1, W2);
    k_bc<<<6, 128>>>(W2, b1, b2);
    k_attend<<<MROWS, 256, SH_TOT * sizeof(float)>>>(X, va);
    k_mlp<<<dim3(48, 12), 256>>>();
    k_final<<<MROWS, 256>>>(W3, b3, out);
}

// round 6
// speedup vs baseline: 1.1135x; 1.1135x over previous
#include <cuda_runtime.h>
#include <cuda_bf16.h>
#include <mma.h>
#include <math.h>
#include <stdint.h>

using namespace nvcuda;

#define EMB   768
#define MROWS 1024
#define NN    128
#define KK    128
#define XROWS (3*EMB+2)   // 2306

// ---------------- device scratch ----------------
__device__ __nv_bfloat16 g_WaHi[KK * 2 * EMB];   // [k=128][e=1536] row-major
__device__ __nv_bfloat16 g_WaLo[KK * 2 * EMB];
__device__ float g_Wc [EMB * EMB];
__device__ float g_bc [EMB];
__device__ float g_P  [(size_t)MROWS * 3 * EMB];
__device__ float g_Z  [(size_t)MROWS * 3 * EMB];

// ---------------- 0) split Wa into bf16 hi/lo ----------------
__global__ void k_split(const float* __restrict__ Wa) {
    int i = blockIdx.x * 256 + threadIdx.x;
    if (i < KK * 2 * EMB) {
        float x = Wa[i];
        __nv_bfloat16 h = __float2bfloat16(x);
        float lo = x - __bfloat162float(h);
        g_WaHi[i] = h;
        g_WaLo[i] = __float2bfloat16(lo);
    }
}

// ---------------- 1) Wc = W2 @ W1 ----------------
__global__ void k_wc(const float* __restrict__ W1, const float* __restrict__ W2) {
    __shared__ float As[64][17];
    __shared__ float Bs[16][65];
    int i0 = blockIdx.y * 64, e0 = blockIdx.x * 64;
    int tx = threadIdx.x & 15, ty = threadIdx.x >> 4;
    float acc[4][4];
#pragma unroll
    for (int i = 0; i < 4; i++)
#pragma unroll
        for (int j = 0; j < 4; j++) acc[i][j] = 0.f;

    for (int t0 = 0; t0 < EMB; t0 += 16) {
        __syncthreads();
        int idx = threadIdx.x;
#pragma unroll
        for (int rep = 0; rep < 4; rep++, idx += 256) {
            int r = idx >> 4, c = idx & 15;
            As[r][c] = W2[(size_t)(i0 + r) * EMB + t0 + c];
        }
        idx = threadIdx.x;
#pragma unroll
        for (int rep = 0; rep < 4; rep++, idx += 256) {
            int r = idx >> 6, c = idx & 63;
            Bs[r][c] = W1[(size_t)(t0 + r) * EMB + e0 + c];
        }
        __syncthreads();
#pragma unroll
        for (int t = 0; t < 16; t++) {
            float a[4], b[4];
#pragma unroll
            for (int u = 0; u < 4; u++) { a[u] = As[ty * 4 + u][t]; b[u] = Bs[t][tx * 4 + u]; }
#pragma unroll
            for (int i = 0; i < 4; i++)
#pragma unroll
                for (int j = 0; j < 4; j++) acc[i][j] += a[i] * b[j];
        }
    }
#pragma unroll
    for (int i = 0; i < 4; i++)
#pragma unroll
        for (int j = 0; j < 4; j++)
            g_Wc[(size_t)(i0 + ty * 4 + i) * EMB + e0 + tx * 4 + j] = acc[i][j];
}

// ---------------- 1b) bc = W2 @ b1 + b2 ----------------
__global__ void k_bc(const float* __restrict__ W2, const float* __restrict__ b1,
                     const float* __restrict__ b2) {
    int i = blockIdx.x * blockDim.x + threadIdx.x;
    if (i < EMB) {
        float s = 0.f;
        for (int j = 0; j < EMB; j++) s += W2[(size_t)i * EMB + j] * b1[j];
        g_bc[i] = s + b2[i];
    }
}

// ---------------- 2) attend: tensor-core version ----------------
// smem byte offsets (all 32B aligned)
#define OF_X1H  0         // 32 x 136 bf16
#define OF_X1L  8704
#define OF_X2H  17408
#define OF_X2L  26112
#define OF_WAH  34816     // 128 x 32 bf16
#define OF_WAL  43008
#define OF_SCR  51200     // 16 warps * 16x20 floats
#define OF_SPART 71680    // 4 * 128 floats
#define OF_SC   73728     // 128 floats
#define OF_BETA 74240
#define OF_RED  74752
#define OF_VA   74768
#define SMEM_BYTES 75280

typedef wmma::fragment<wmma::matrix_a, 16, 16, 16, __nv_bfloat16, wmma::row_major> FragA;
typedef wmma::fragment<wmma::matrix_b, 16, 16, 16, __nv_bfloat16, wmma::row_major> FragB;
typedef wmma::fragment<wmma::accumulator, 16, 16, 16, float> FragC;

__device__ __forceinline__ float tanh_fast(float x) {
    float y;
    asm("tanh.approx.f32 %0, %1;" : "=f"(y) : "f"(x));
    return y;
}

// stage 128x32 Wa hi/lo chunk (cols eg0..eg0+31) into smem
__device__ __forceinline__ void stage_wa(char* sb, int eg0, int tid) {
    uint2* dh = (uint2*)(sb + OF_WAH);
    uint2* dl = (uint2*)(sb + OF_WAL);
#pragma unroll
    for (int r = 0; r < 2; r++) {
        int l = tid + r * 512;            // 0..1023, 8 uint2 per row
        int row = l >> 3, c = l & 7;
        const uint2* sh = (const uint2*)(g_WaHi + (size_t)row * (2 * EMB) + eg0);
        const uint2* sl = (const uint2*)(g_WaLo + (size_t)row * (2 * EMB) + eg0);
        dh[row * 8 + c] = sh[c];
        dl[row * 8 + c] = sl[c];
    }
}

// stage 32x128 fp32 X rows -> bf16 hi/lo smem tiles [32][136]
__device__ __forceinline__ void stage_x(char* sb, int offH, int offL,
                                        const float* __restrict__ src, int tid) {
    __nv_bfloat16* dh = (__nv_bfloat16*)(sb + offH);
    __nv_bfloat16* dl = (__nv_bfloat16*)(sb + offL);
#pragma unroll
    for (int r = 0; r < 2; r++) {
        int l = tid + r * 512;            // 0..1023 float4s (32x32)
        int row = l >> 5, c4 = l & 31;
        float4 v = ((const float4*)(src + (size_t)row * NN))[c4];
        __nv_bfloat16 hx = __float2bfloat16(v.x);
        __nv_bfloat16 hy = __float2bfloat16(v.y);
        __nv_bfloat16 hz = __float2bfloat16(v.z);
        __nv_bfloat16 hw = __float2bfloat16(v.w);
        __nv_bfloat16 lx = __float2bfloat16(v.x - __bfloat162float(hx));
        __nv_bfloat16 ly = __float2bfloat16(v.y - __bfloat162float(hy));
        __nv_bfloat16 lz = __float2bfloat16(v.z - __bfloat162float(hz));
        __nv_bfloat16 lw = __float2bfloat16(v.w - __bfloat162float(hw));
        __nv_bfloat162* ph = (__nv_bfloat162*)(dh + row * 136 + c4 * 4);
        __nv_bfloat162* pl = (__nv_bfloat162*)(dl + row * 136 + c4 * 4);
        ph[0] = __nv_bfloat162(hx, hy);  ph[1] = __nv_bfloat162(hz, hw);
        pl[0] = __nv_bfloat162(lx, ly);  pl[1] = __nv_bfloat162(lz, lw);
    }
}

template <int NP>
__device__ __forceinline__ void mma_chunk(FragC (&acc)[2][2][2], const char* sb,
                                          int wk, int wn) {
    const __nv_bfloat16* wah = (const __nv_bfloat16*)(sb + OF_WAH);
    const __nv_bfloat16* wal = (const __nv_bfloat16*)(sb + OF_WAL);
#pragma unroll
    for (int ks = 0; ks < 2; ks++) {
        int ek = ks * 16;
        FragA aH[2], aL[2];
#pragma unroll
        for (int f = 0; f < 2; f++) {
            wmma::load_matrix_sync(aH[f], wah + (wk * 32 + f * 16) * 32 + ek, 32);
            wmma::load_matrix_sync(aL[f], wal + (wk * 32 + f * 16) * 32 + ek, 32);
        }
#pragma unroll
        for (int p = 0; p < NP; p++) {
            const __nv_bfloat16* xh =
                (const __nv_bfloat16*)(sb + (p ? OF_X2H : OF_X1H));
            const __nv_bfloat16* xl =
                (const __nv_bfloat16*)(sb + (p ? OF_X2L : OF_X1L));
#pragma unroll
            for (int fn = 0; fn < 2; fn++) {
                FragB bH, bL;
                wmma::load_matrix_sync(bH, xh + ek * 136 + wn * 32 + fn * 16, 136);
                wmma::load_matrix_sync(bL, xl + ek * 136 + wn * 32 + fn * 16, 136);
#pragma unroll
                for (int fk = 0; fk < 2; fk++) {
                    wmma::mma_sync(acc[p][fk][fn], aH[fk], bH, acc[p][fk][fn]);
                    wmma::mma_sync(acc[p][fk][fn], aH[fk], bL, acc[p][fk][fn]);
                    wmma::mma_sync(acc[p][fk][fn], aL[fk], bH, acc[p][fk][fn]);
                }
            }
        }
    }
}

__global__ __launch_bounds__(512, 1)
void k_attend(const float* __restrict__ X, const float* __restrict__ va) {
    extern __shared__ char sb[];
    int m    = blockIdx.x;
    int tid  = threadIdx.x;
    int wid  = tid >> 5, lane = tid & 31;
    int wk   = wid & 3, wn = wid >> 2;
    const float* Xm = X + (size_t)m * XROWS * NN;

    float* vas   = (float*)(sb + OF_VA);
    float* spart = (float*)(sb + OF_SPART);
    float* scs   = (float*)(sb + OF_SC);
    float* beta  = (float*)(sb + OF_BETA);
    float* red   = (float*)(sb + OF_RED);
    float* scr   = (float*)(sb + OF_SCR) + wid * 320;   // 16x20 per warp

    if (tid < 128) vas[tid] = va[tid];

    FragC acc[2][2][2];
#pragma unroll
    for (int fk = 0; fk < 2; fk++)
#pragma unroll
        for (int fn = 0; fn < 2; fn++) wmma::fill_fragment(acc[0][fk][fn], 0.f);

    // ---- Phase A: hq ----
    for (int e0 = 0; e0 < EMB; e0 += 32) {
        __syncthreads();
        stage_wa(sb, e0, tid);
        stage_x(sb, OF_X1H, OF_X1L, Xm + (size_t)e0 * NN, tid);
        __syncthreads();
        mma_chunk<1>(acc, sb, wk, wn);
    }

    // acc1 = copy(hq)
#pragma unroll
    for (int fk = 0; fk < 2; fk++)
#pragma unroll
        for (int fn = 0; fn < 2; fn++)
#pragma unroll
            for (int i = 0; i < acc[0][fk][fn].num_elements; i++)
                acc[1][fk][fn].x[i] = acc[0][fk][fn].x[i];

    // ---- combined pool GEMMs (shared Wa_p tiles) ----
    for (int e0 = 0; e0 < EMB; e0 += 32) {
        __syncthreads();
        stage_wa(sb, EMB + e0, tid);
        stage_x(sb, OF_X1H, OF_X1L, Xm + (size_t)(EMB + e0) * NN, tid);
        stage_x(sb, OF_X2H, OF_X2L, Xm + (size_t)(2 * EMB + 1 + e0) * NN, tid);
        __syncthreads();
        mma_chunk<2>(acc, sb, wk, wn);
    }
    __syncthreads();

    // ---- per-pool: score -> softmax -> pooling ----
#pragma unroll 1
    for (int p = 0; p < 2; p++) {
        const int exp0 = (p == 0) ? EMB : (2 * EMB + 1);
        const int ev   = (p == 0) ? (2 * EMB) : (3 * EMB + 1);

        int j = lane & 15, rh = (lane >> 4) * 8;
#pragma unroll
        for (int fn = 0; fn < 2; fn++) {
            float ps = 0.f;
#pragma unroll
            for (int fk = 0; fk < 2; fk++) {
                wmma::store_matrix_sync(scr, acc[p][fk][fn], 20, wmma::mem_row_major);
                __syncwarp();
#pragma unroll
                for (int r = 0; r < 8; r++) {
                    int k = wk * 32 + fk * 16 + rh + r;
                    ps += vas[k] * tanh_fast(scr[(rh + r) * 20 + j]);
                }
                __syncwarp();
            }
            ps += __shfl_xor_sync(0xffffffffu, ps, 16);
            if (lane < 16)
                spart[wk * 128 + wn * 32 + fn * 16 + lane] = ps;
        }
        __syncthreads();

        if (tid < 128) {
            float sc = spart[tid] + spart[128 + tid] + spart[256 + tid] + spart[384 + tid];
            scs[tid] = sc * Xm[(size_t)ev * NN + tid];
        }
        __syncthreads();
        if (tid < 32) {
            float mx = fmaxf(fmaxf(scs[tid], scs[tid + 32]),
                             fmaxf(scs[tid + 64], scs[tid + 96]));
#pragma unroll
            for (int off = 16; off; off >>= 1)
                mx = fmaxf(mx, __shfl_xor_sync(0xffffffffu, mx, off));
            if (tid == 0) red[0] = mx;
        }
        __syncthreads();
        float mx = red[0];
        if (tid < 128) beta[tid] = expf(scs[tid] - mx);
        __syncthreads();
        if (tid < 32) {
            float s = beta[tid] + beta[tid + 32] + beta[tid + 64] + beta[tid + 96];
#pragma unroll
            for (int off = 16; off; off >>= 1)
                s += __shfl_xor_sync(0xffffffffu, s, off);
            if (tid == 0) red[0] = s;
        }
        __syncthreads();
        float inv = 1.f / red[0];
        if (tid < 128) beta[tid] *= inv;
        __syncthreads();

        // pooling: p[e] = sum_n beta[n] * Xp[e][n]
        for (int e = wid; e < EMB; e += 16) {
            const float* row = Xm + (size_t)(exp0 + e) * NN;
            float s = row[lane]      * beta[lane]      +
                      row[lane + 32] * beta[lane + 32] +
                      row[lane + 64] * beta[lane + 64] +
                      row[lane + 96] * beta[lane + 96];
#pragma unroll
            for (int off = 16; off; off >>= 1)
                s += __shfl_xor_sync(0xffffffffu, s, off);
            if (lane == 0) g_P[((size_t)m * 3 + p) * EMB + e] = s;
        }
        __syncthreads();
    }

    // qv[e] = Xq[e][0]
    for (int e = tid; e < EMB; e += 512)
        g_P[((size_t)m * 3 + 2) * EMB + e] = Xm[(size_t)e * NN];
}

// ---------------- 3) MLP: Z = relu(P @ Wc^T + bc) ----------------
__global__ __launch_bounds__(256) void k_mlp() {
    __shared__ float As[64][33];
    __shared__ float Bs[64][33];
    int r0 = blockIdx.x * 64, i0 = blockIdx.y * 64;
    int tx = threadIdx.x & 15, ty = threadIdx.x >> 4;
    float acc[4][4];
#pragma unroll
    for (int i = 0; i < 4; i++)
#pragma unroll
        for (int j = 0; j < 4; j++) acc[i][j] = 0.f;

    for (int e0 = 0; e0 < EMB; e0 += 32) {
        __syncthreads();
        for (int idx = threadIdx.x; idx < 64 * 32; idx += 256) {
            int r = idx >> 5, c = idx & 31;
            As[r][c] = g_P[(size_t)(r0 + r) * EMB + e0 + c];
            Bs[r][c] = g_Wc[(size_t)(i0 + r) * EMB + e0 + c];
        }
        __syncthreads();
#pragma unroll 8
        for (int ec = 0; ec < 32; ec++) {
            float a[4], b[4];
#pragma unroll
            for (int u = 0; u < 4; u++) {
                a[u] = As[ty * 4 + u][ec];
                b[u] = Bs[tx * 4 + u][ec];
            }
#pragma unroll
            for (int i = 0; i < 4; i++)
#pragma unroll
                for (int j = 0; j < 4; j++) acc[i][j] += a[i] * b[j];
        }
    }
#pragma unroll
    for (int i = 0; i < 4; i++)
#pragma unroll
        for (int j = 0; j < 4; j++) {
            int r = r0 + ty * 4 + i, ii = i0 + tx * 4 + j;
            g_Z[(size_t)r * EMB + ii] = fmaxf(acc[i][j] + g_bc[ii], 0.f);
        }
}

// ---------------- 4) final head ----------------
__global__ void k_final(const float* __restrict__ W3, const float* __restrict__ b3,
                        float* __restrict__ out) {
    __shared__ float red[8];
    int m = blockIdx.x;
    const float* z1 = g_Z + (size_t)m * 3 * EMB;
    const float* z2 = z1 + EMB;
    const float* zq = z1 + 2 * EMB;
    float s = 0.f;
    for (int i = threadIdx.x; i < EMB; i += 256) {
        float a = z1[i], b = z2[i], q = zq[i];
        s += W3[i] * a + W3[EMB + i] * b +
             W3[2 * EMB + i] * fabsf(a - b) +
             W3[3 * EMB + i] * fabsf(a - q) +
             W3[4 * EMB + i] * fabsf(b - q);
    }
#pragma unroll
    for (int off = 16; off; off >>= 1)
        s += __shfl_xor_sync(0xffffffffu, s, off);
    if ((threadIdx.x & 31) == 0) red[threadIdx.x >> 5] = s;
    __syncthreads();
    if (threadIdx.x == 0) {
        float t = 0.f;
#pragma unroll
        for (int w = 0; w < 8; w++) t += red[w];
        out[m] = fmaxf(t + b3[0], 0.f);
    }
}

// ---------------- launch ----------------
extern "C" void kernel_launch(void* const* d_in, const int* in_sizes, int n_in,
                              void* d_out, int out_size) {
    (void)in_sizes; (void)n_in; (void)out_size;
    const float* X  = (const float*)d_in[0];
    const float* Wa = (const float*)d_in[1];
    const float* va = (const float*)d_in[2];
    const float* W1 = (const float*)d_in[3];
    const float* b1 = (const float*)d_in[4];
    const float* W2 = (const float*)d_in[5];
    const float* b2 = (const float*)d_in[6];
    const float* W3 = (const float*)d_in[7];
    const float* b3 = (const float*)d_in[8];
    float* out = (float*)d_out;

    static int smem_set = 0;
    if (!smem_set) {
        cudaFuncSetAttribute(k_attend, cudaFuncAttributeMaxDynamicSharedMemorySize,
                             SMEM_BYTES);
        smem_set = 1;
    }

    k_split<<<768, 256>>>(Wa);
    k_wc<<<dim3(12, 12), 256>>>(W1, W2);
    k_bc<<<6, 128>>>(W2, b1, b2);
    k_attend<<<MROWS, 512, SMEM_BYTES>>>(X, va);
    k_mlp<<<dim3(48, 12), 256>>>();
    k_final<<<MROWS, 256>>>(W3, b3, out);
}

// round 7
// speedup vs baseline: 1.1379x; 1.0220x over previous
#include <cuda_runtime.h>
#include <cuda_bf16.h>
#include <mma.h>
#include <math.h>
#include <stdint.h>

using namespace nvcuda;

#define EMB   768
#define MROWS 1024
#define NN    128
#define KK    128
#define XROWS (3*EMB+2)   // 2306

// ---------------- device scratch ----------------
__device__ __nv_bfloat16 g_WaHi[KK * 2 * EMB];
__device__ __nv_bfloat16 g_WaLo[KK * 2 * EMB];
__device__ float g_Wc [EMB * EMB];
__device__ __nv_bfloat16 g_WcHi[EMB * EMB];
__device__ __nv_bfloat16 g_WcLo[EMB * EMB];
__device__ float g_bc [EMB];
__device__ __nv_bfloat16 g_PHi[(size_t)MROWS * 3 * EMB];
__device__ __nv_bfloat16 g_PLo[(size_t)MROWS * 3 * EMB];
__device__ float g_Z  [(size_t)MROWS * 3 * EMB];

// ---------------- 0) split Wa ----------------
__global__ void k_split(const float* __restrict__ Wa) {
    int i = blockIdx.x * 256 + threadIdx.x;
    if (i < KK * 2 * EMB) {
        float x = Wa[i];
        __nv_bfloat16 h = __float2bfloat16(x);
        g_WaHi[i] = h;
        g_WaLo[i] = __float2bfloat16(x - __bfloat162float(h));
    }
}

// ---------------- 1) Wc = W2 @ W1 ----------------
__global__ void k_wc(const float* __restrict__ W1, const float* __restrict__ W2) {
    __shared__ float As[64][17];
    __shared__ float Bs[16][65];
    int i0 = blockIdx.y * 64, e0 = blockIdx.x * 64;
    int tx = threadIdx.x & 15, ty = threadIdx.x >> 4;
    float acc[4][4];
#pragma unroll
    for (int i = 0; i < 4; i++)
#pragma unroll
        for (int j = 0; j < 4; j++) acc[i][j] = 0.f;

    for (int t0 = 0; t0 < EMB; t0 += 16) {
        __syncthreads();
        int idx = threadIdx.x;
#pragma unroll
        for (int rep = 0; rep < 4; rep++, idx += 256) {
            int r = idx >> 4, c = idx & 15;
            As[r][c] = W2[(size_t)(i0 + r) * EMB + t0 + c];
        }
        idx = threadIdx.x;
#pragma unroll
        for (int rep = 0; rep < 4; rep++, idx += 256) {
            int r = idx >> 6, c = idx & 63;
            Bs[r][c] = W1[(size_t)(t0 + r) * EMB + e0 + c];
        }
        __syncthreads();
#pragma unroll
        for (int t = 0; t < 16; t++) {
            float a[4], b[4];
#pragma unroll
            for (int u = 0; u < 4; u++) { a[u] = As[ty * 4 + u][t]; b[u] = Bs[t][tx * 4 + u]; }
#pragma unroll
            for (int i = 0; i < 4; i++)
#pragma unroll
                for (int j = 0; j < 4; j++) acc[i][j] += a[i] * b[j];
        }
    }
#pragma unroll
    for (int i = 0; i < 4; i++)
#pragma unroll
        for (int j = 0; j < 4; j++)
            g_Wc[(size_t)(i0 + ty * 4 + i) * EMB + e0 + tx * 4 + j] = acc[i][j];
}

// ---------------- 1b) bc = W2 @ b1 + b2; split Wc ----------------
__global__ void k_bc(const float* __restrict__ W2, const float* __restrict__ b1,
                     const float* __restrict__ b2) {
    int i = blockIdx.x * blockDim.x + threadIdx.x;
    if (i < EMB) {
        float s = 0.f;
        for (int j = 0; j < EMB; j++) s += W2[(size_t)i * EMB + j] * b1[j];
        g_bc[i] = s + b2[i];
    }
}

__global__ void k_wcsplit() {
    int i = blockIdx.x * 256 + threadIdx.x;
    if (i < EMB * EMB) {
        float x = g_Wc[i];
        __nv_bfloat16 h = __float2bfloat16(x);
        g_WcHi[i] = h;
        g_WcLo[i] = __float2bfloat16(x - __bfloat162float(h));
    }
}

// ---------------- 2) attend: pipelined tensor-core version ----------------
// per-buffer offsets
#define OF_X1H  0         // 32 x 136 bf16
#define OF_X1L  8704
#define OF_X2H  17408
#define OF_X2L  26112
#define OF_WAH  34816     // 128 x 32 bf16
#define OF_WAL  43008
#define BUF_STRIDE 51200
// shared tail
#define OF_SCR   102400   // 16 warps * 320 floats
#define OF_SPART 122880
#define OF_SC    124928
#define OF_BETA  125440
#define OF_RED   125952
#define OF_VA    125968
#define SMEM_BYTES 126480

typedef wmma::fragment<wmma::matrix_a, 16, 16, 16, __nv_bfloat16, wmma::row_major> FragA;
typedef wmma::fragment<wmma::matrix_b, 16, 16, 16, __nv_bfloat16, wmma::row_major> FragB;
typedef wmma::fragment<wmma::accumulator, 16, 16, 16, float> FragC;

__device__ __forceinline__ float tanh_fast(float x) {
    float y;
    asm("tanh.approx.f32 %0, %1;" : "=f"(y) : "f"(x));
    return y;
}

__device__ __forceinline__ void ldg_x(float4 (&p)[2], const float* __restrict__ src, int tid) {
#pragma unroll
    for (int r = 0; r < 2; r++) {
        int l = tid + r * 512;
        p[r] = __ldg((const float4*)(src + (size_t)(l >> 5) * NN) + (l & 31));
    }
}

__device__ __forceinline__ void ldg_wa(uint2 (&ph)[2], uint2 (&pl)[2], int eg0, int tid) {
#pragma unroll
    for (int r = 0; r < 2; r++) {
        int l = tid + r * 512;
        int row = l >> 3, c = l & 7;
        ph[r] = *((const uint2*)(g_WaHi + (size_t)row * (2 * EMB) + eg0) + c);
        pl[r] = *((const uint2*)(g_WaLo + (size_t)row * (2 * EMB) + eg0) + c);
    }
}

__device__ __forceinline__ void sts_x(char* sbuf, int offH, int offL,
                                      const float4 (&p)[2], int tid) {
    __nv_bfloat16* dh = (__nv_bfloat16*)(sbuf + offH);
    __nv_bfloat16* dl = (__nv_bfloat16*)(sbuf + offL);
#pragma unroll
    for (int r = 0; r < 2; r++) {
        int l = tid + r * 512;
        int row = l >> 5, c4 = l & 31;
        float4 v = p[r];
        __nv_bfloat16 hx = __float2bfloat16(v.x);
        __nv_bfloat16 hy = __float2bfloat16(v.y);
        __nv_bfloat16 hz = __float2bfloat16(v.z);
        __nv_bfloat16 hw = __float2bfloat16(v.w);
        __nv_bfloat16 lx = __float2bfloat16(v.x - __bfloat162float(hx));
        __nv_bfloat16 ly = __float2bfloat16(v.y - __bfloat162float(hy));
        __nv_bfloat16 lz = __float2bfloat16(v.z - __bfloat162float(hz));
        __nv_bfloat16 lw = __float2bfloat16(v.w - __bfloat162float(hw));
        __nv_bfloat162* ph = (__nv_bfloat162*)(dh + row * 136 + c4 * 4);
        __nv_bfloat162* pl2 = (__nv_bfloat162*)(dl + row * 136 + c4 * 4);
        ph[0] = __nv_bfloat162(hx, hy);  ph[1] = __nv_bfloat162(hz, hw);
        pl2[0] = __nv_bfloat162(lx, ly); pl2[1] = __nv_bfloat162(lz, lw);
    }
}

__device__ __forceinline__ void sts_wa(char* sbuf, const uint2 (&ph)[2],
                                       const uint2 (&pl)[2], int tid) {
#pragma unroll
    for (int r = 0; r < 2; r++) {
        int l = tid + r * 512;
        int row = l >> 3, c = l & 7;
        ((uint2*)(sbuf + OF_WAH))[row * 8 + c] = ph[r];
        ((uint2*)(sbuf + OF_WAL))[row * 8 + c] = pl[r];
    }
}

template <int NP>
__device__ __forceinline__ void mma_chunk(FragC (&acc)[2][2][2], const char* sbuf,
                                          int wk, int wn) {
    const __nv_bfloat16* wah = (const __nv_bfloat16*)(sbuf + OF_WAH);
    const __nv_bfloat16* wal = (const __nv_bfloat16*)(sbuf + OF_WAL);
#pragma unroll
    for (int ks = 0; ks < 2; ks++) {
        int ek = ks * 16;
        FragA aH[2], aL[2];
#pragma unroll
        for (int f = 0; f < 2; f++) {
            wmma::load_matrix_sync(aH[f], wah + (wk * 32 + f * 16) * 32 + ek, 32);
            wmma::load_matrix_sync(aL[f], wal + (wk * 32 + f * 16) * 32 + ek, 32);
        }
#pragma unroll
        for (int p = 0; p < NP; p++) {
            const __nv_bfloat16* xh = (const __nv_bfloat16*)(sbuf + (p ? OF_X2H : OF_X1H));
            const __nv_bfloat16* xl = (const __nv_bfloat16*)(sbuf + (p ? OF_X2L : OF_X1L));
#pragma unroll
            for (int fn = 0; fn < 2; fn++) {
                FragB bH, bL;
                wmma::load_matrix_sync(bH, xh + ek * 136 + wn * 32 + fn * 16, 136);
                wmma::load_matrix_sync(bL, xl + ek * 136 + wn * 32 + fn * 16, 136);
#pragma unroll
                for (int fk = 0; fk < 2; fk++) {
                    wmma::mma_sync(acc[p][fk][fn], aH[fk], bH, acc[p][fk][fn]);
                    wmma::mma_sync(acc[p][fk][fn], aH[fk], bL, acc[p][fk][fn]);
                    wmma::mma_sync(acc[p][fk][fn], aL[fk], bH, acc[p][fk][fn]);
                }
            }
        }
    }
}

__global__ __launch_bounds__(512, 1)
void k_attend(const float* __restrict__ X, const float* __restrict__ va) {
    extern __shared__ char sb[];
    int m    = blockIdx.x;
    int tid  = threadIdx.x;
    int wid  = tid >> 5, lane = tid & 31;
    int wk   = wid & 3, wn = wid >> 2;
    const float* Xm = X + (size_t)m * XROWS * NN;

    float* vas   = (float*)(sb + OF_VA);
    float* spart = (float*)(sb + OF_SPART);
    float* scs   = (float*)(sb + OF_SC);
    float* beta  = (float*)(sb + OF_BETA);
    float* red   = (float*)(sb + OF_RED);
    float* scr   = (float*)(sb + OF_SCR) + wid * 320;

    if (tid < 128) vas[tid] = va[tid];

    FragC acc[2][2][2];
#pragma unroll
    for (int fk = 0; fk < 2; fk++)
#pragma unroll
        for (int fn = 0; fn < 2; fn++) wmma::fill_fragment(acc[0][fk][fn], 0.f);

    float4 px1[2], px2[2];
    uint2 pwh[2], pwl[2];
    int cg = 0;

    // prefetch chunk 0 of phase A
    ldg_x(px1, Xm, tid);
    ldg_wa(pwh, pwl, 0, tid);

    // ---- Phase A: hq (24 chunks) ----
#pragma unroll 1
    for (int c = 0; c < 24; c++) {
        char* buf = sb + (cg & 1) * BUF_STRIDE;
        sts_x(buf, OF_X1H, OF_X1L, px1, tid);
        sts_wa(buf, pwh, pwl, tid);
        __syncthreads();
        if (c < 23) {
            ldg_x(px1, Xm + (size_t)(c + 1) * 32 * NN, tid);
            ldg_wa(pwh, pwl, (c + 1) * 32, tid);
        } else {
            ldg_x(px1, Xm + (size_t)EMB * NN, tid);
            ldg_x(px2, Xm + (size_t)(2 * EMB + 1) * NN, tid);
            ldg_wa(pwh, pwl, EMB, tid);
        }
        mma_chunk<1>(acc, buf, wk, wn);
        cg++;
    }

    // acc1 = copy(hq)
#pragma unroll
    for (int fk = 0; fk < 2; fk++)
#pragma unroll
        for (int fn = 0; fn < 2; fn++)
#pragma unroll
            for (int i = 0; i < acc[0][fk][fn].num_elements; i++)
                acc[1][fk][fn].x[i] = acc[0][fk][fn].x[i];

    // ---- Phase B: both pool GEMMs (24 chunks, shared Wa_p tiles) ----
#pragma unroll 1
    for (int c = 0; c < 24; c++) {
        char* buf = sb + (cg & 1) * BUF_STRIDE;
        sts_x(buf, OF_X1H, OF_X1L, px1, tid);
        sts_x(buf, OF_X2H, OF_X2L, px2, tid);
        sts_wa(buf, pwh, pwl, tid);
        __syncthreads();
        if (c < 23) {
            int e1 = (c + 1) * 32;
            ldg_x(px1, Xm + (size_t)(EMB + e1) * NN, tid);
            ldg_x(px2, Xm + (size_t)(2 * EMB + 1 + e1) * NN, tid);
            ldg_wa(pwh, pwl, EMB + e1, tid);
        }
        mma_chunk<2>(acc, buf, wk, wn);
        cg++;
    }
    __syncthreads();

    // ---- per-pool: score -> softmax -> pooling ----
#pragma unroll 1
    for (int p = 0; p < 2; p++) {
        const int exp0 = (p == 0) ? EMB : (2 * EMB + 1);
        const int ev   = (p == 0) ? (2 * EMB) : (3 * EMB + 1);

        int j = lane & 15, rh = (lane >> 4) * 8;
#pragma unroll
        for (int fn = 0; fn < 2; fn++) {
            float ps = 0.f;
#pragma unroll
            for (int fk = 0; fk < 2; fk++) {
                wmma::store_matrix_sync(scr, acc[p][fk][fn], 20, wmma::mem_row_major);
                __syncwarp();
#pragma unroll
                for (int r = 0; r < 8; r++) {
                    int k = wk * 32 + fk * 16 + rh + r;
                    ps += vas[k] * tanh_fast(scr[(rh + r) * 20 + j]);
                }
                __syncwarp();
            }
            ps += __shfl_xor_sync(0xffffffffu, ps, 16);
            if (lane < 16)
                spart[wk * 128 + wn * 32 + fn * 16 + lane] = ps;
        }
        __syncthreads();

        if (tid < 128) {
            float sc = spart[tid] + spart[128 + tid] + spart[256 + tid] + spart[384 + tid];
            scs[tid] = sc * Xm[(size_t)ev * NN + tid];
        }
        __syncthreads();
        if (tid < 32) {
            float mx = fmaxf(fmaxf(scs[tid], scs[tid + 32]),
                             fmaxf(scs[tid + 64], scs[tid + 96]));
#pragma unroll
            for (int off = 16; off; off >>= 1)
                mx = fmaxf(mx, __shfl_xor_sync(0xffffffffu, mx, off));
            if (tid == 0) red[0] = mx;
        }
        __syncthreads();
        float mx = red[0];
        if (tid < 128) beta[tid] = expf(scs[tid] - mx);
        __syncthreads();
        if (tid < 32) {
            float s = beta[tid] + beta[tid + 32] + beta[tid + 64] + beta[tid + 96];
#pragma unroll
            for (int off = 16; off; off >>= 1)
                s += __shfl_xor_sync(0xffffffffu, s, off);
            if (tid == 0) red[0] = s;
        }
        __syncthreads();
        float inv = 1.f / red[0];
        if (tid < 128) beta[tid] *= inv;
        __syncthreads();

        // pooling: p[e] = sum_n beta[n] * Xp[e][n]
        for (int e = wid; e < EMB; e += 16) {
            const float* row = Xm + (size_t)(exp0 + e) * NN;
            float s = row[lane]      * beta[lane]      +
                      row[lane + 32] * beta[lane + 32] +
                      row[lane + 64] * beta[lane + 64] +
                      row[lane + 96] * beta[lane + 96];
#pragma unroll
            for (int off = 16; off; off >>= 1)
                s += __shfl_xor_sync(0xffffffffu, s, off);
            if (lane == 0) {
                size_t o = ((size_t)m * 3 + p) * EMB + e;
                __nv_bfloat16 h = __float2bfloat16(s);
                g_PHi[o] = h;
                g_PLo[o] = __float2bfloat16(s - __bfloat162float(h));
            }
        }
        __syncthreads();
    }

    // qv[e] = Xq[e][0]
    for (int e = tid; e < EMB; e += 512) {
        float s = Xm[(size_t)e * NN];
        size_t o = ((size_t)m * 3 + 2) * EMB + e;
        __nv_bfloat16 h = __float2bfloat16(s);
        g_PHi[o] = h;
        g_PLo[o] = __float2bfloat16(s - __bfloat162float(h));
    }
}

// ---------------- 3) MLP: Z = relu(P @ Wc^T + bc), tensor cores ----------
typedef wmma::fragment<wmma::matrix_b, 16, 16, 16, __nv_bfloat16, wmma::col_major> FragBc;

__global__ __launch_bounds__(256) void k_mlp() {
    __shared__ __nv_bfloat16 Ah[128][40], Al[128][40];   // P tile  [row][e]
    __shared__ __nv_bfloat16 Bh[128][40], Bl[128][40];   // Wc tile [i][e]
    int r0 = blockIdx.x * 128, i0 = blockIdx.y * 128;
    int tid = threadIdx.x;
    int wid = tid >> 5, lane = tid & 31;
    int wm = wid & 1, wn = wid >> 1;   // 2 x 4 warps; warp tile 64m x 32n

    FragC acc[4][2];
#pragma unroll
    for (int i = 0; i < 4; i++)
#pragma unroll
        for (int j = 0; j < 2; j++) wmma::fill_fragment(acc[i][j], 0.f);

#pragma unroll 1
    for (int e0 = 0; e0 < EMB; e0 += 32) {
        __syncthreads();
#pragma unroll
        for (int k = 0; k < 4; k++) {
            int l = tid + k * 256;      // 1024 uint2 per tile
            int row = l >> 3, c = l & 7;
            *(uint2*)&Ah[row][c * 4] = *((const uint2*)(g_PHi + (size_t)(r0 + row) * EMB + e0) + c);
            *(uint2*)&Al[row][c * 4] = *((const uint2*)(g_PLo + (size_t)(r0 + row) * EMB + e0) + c);
            *(uint2*)&Bh[row][c * 4] = *((const uint2*)(g_WcHi + (size_t)(i0 + row) * EMB + e0) + c);
            *(uint2*)&Bl[row][c * 4] = *((const uint2*)(g_WcLo + (size_t)(i0 + row) * EMB + e0) + c);
        }
        __syncthreads();
#pragma unroll
        for (int ks = 0; ks < 2; ks++) {
            int ek = ks * 16;
            FragBc bh[2], bl[2];
#pragma unroll
            for (int fn = 0; fn < 2; fn++) {
                wmma::load_matrix_sync(bh[fn], &Bh[wn * 32 + fn * 16][ek], 40);
                wmma::load_matrix_sync(bl[fn], &Bl[wn * 32 + fn * 16][ek], 40);
            }
#pragma unroll
            for (int fm = 0; fm < 4; fm++) {
                FragA ah, al;
                wmma::load_matrix_sync(ah, &Ah[wm * 64 + fm * 16][ek], 40);
                wmma::load_matrix_sync(al, &Al[wm * 64 + fm * 16][ek], 40);
#pragma unroll
                for (int fn = 0; fn < 2; fn++) {
                    wmma::mma_sync(acc[fm][fn], ah, bh[fn], acc[fm][fn]);
                    wmma::mma_sync(acc[fm][fn], ah, bl[fn], acc[fm][fn]);
                    wmma::mma_sync(acc[fm][fn], al, bh[fn], acc[fm][fn]);
                }
            }
        }
    }
    __syncthreads();   // tiles done; reuse Ah region as scratch

    float* scr = (float*)&Ah[0][0] + wid * 320;   // 16x20 per warp
#pragma unroll
    for (int fm = 0; fm < 4; fm++)
#pragma unroll
        for (int fn = 0; fn < 2; fn++) {
            wmma::store_matrix_sync(scr, acc[fm][fn], 20, wmma::mem_row_major);
            __syncwarp();
#pragma unroll
            for (int u = 0; u < 8; u++) {
                int el = lane + u * 32;         // 0..255
                int r = el >> 4, c = el & 15;
                int gi = i0 + wn * 32 + fn * 16 + c;
                int gr = r0 + wm * 64 + fm * 16 + r;
                g_Z[(size_t)gr * EMB + gi] = fmaxf(scr[r * 20 + c] + g_bc[gi], 0.f);
            }
            __syncwarp();
        }
}

// ---------------- 4) final head ----------------
__global__ void k_final(const float* __restrict__ W3, const float* __restrict__ b3,
                        float* __restrict__ out) {
    __shared__ float red[8];
    int m = blockIdx.x;
    const float* z1 = g_Z + (size_t)m * 3 * EMB;
    const float* z2 = z1 + EMB;
    const float* zq = z1 + 2 * EMB;
    float s = 0.f;
    for (int i = threadIdx.x; i < EMB; i += 256) {
        float a = z1[i], b = z2[i], q = zq[i];
        s += W3[i] * a + W3[EMB + i] * b +
             W3[2 * EMB + i] * fabsf(a - b) +
             W3[3 * EMB + i] * fabsf(a - q) +
             W3[4 * EMB + i] * fabsf(b - q);
    }
#pragma unroll
    for (int off = 16; off; off >>= 1)
        s += __shfl_xor_sync(0xffffffffu, s, off);
    if ((threadIdx.x & 31) == 0) red[threadIdx.x >> 5] = s;
    __syncthreads();
    if (threadIdx.x == 0) {
        float t = 0.f;
#pragma unroll
        for (int w = 0; w < 8; w++) t += red[w];
        out[m] = fmaxf(t + b3[0], 0.f);
    }
}

// ---------------- launch ----------------
extern "C" void kernel_launch(void* const* d_in, const int* in_sizes, int n_in,
                              void* d_out, int out_size) {
    (void)in_sizes; (void)n_in; (void)out_size;
    const float* X  = (const float*)d_in[0];
    const float* Wa = (const float*)d_in[1];
    const float* va = (const float*)d_in[2];
    const float* W1 = (const float*)d_in[3];
    const float* b1 = (const float*)d_in[4];
    const float* W2 = (const float*)d_in[5];
    const float* b2 = (const float*)d_in[6];
    const float* W3 = (const float*)d_in[7];
    const float* b3 = (const float*)d_in[8];
    float* out = (float*)d_out;

    static int smem_set = 0;
    if (!smem_set) {
        cudaFuncSetAttribute(k_attend, cudaFuncAttributeMaxDynamicSharedMemorySize,
                             SMEM_BYTES);
        smem_set = 1;
    }

    k_split<<<768, 256>>>(Wa);
    k_wc<<<dim3(12, 12), 256>>>(W1, W2);
    k_bc<<<6, 128>>>(W2, b1, b2);
    k_wcsplit<<<(EMB * EMB + 255) / 256, 256>>>();
    k_attend<<<MROWS, 512, SMEM_BYTES>>>(X, va);
    k_mlp<<<dim3(24, 6), 256>>>();
    k_final<<<MROWS, 256>>>(W3, b3, out);
}